// round 13
// baseline (speedup 1.0000x reference)
#include <cuda_runtime.h>
#include <cuda_fp16.h>
#include <math.h>
#include <stdint.h>

// ---------------------------------------------------------------------------
// PairwiseAttention round 10: round-9 fusions (LN in A-staging, weight cast
// in B-staging) but QKV restored to grid (3 n-chunks, 512 m-tiles) so block-
// level overlap hides staging latency (round-9's serial 3-chunk loop was the
// regression). Attn keeps K-fragment double buffer.
// ---------------------------------------------------------------------------

#define L 256
#define D 128
#define NH 4
#define HD 32
#define M_TOTAL (L * L)          // 65536
#define QKV_N (3 * D)            // 384
#define QSCALE 0.17677669529663687f   // 1/sqrt(32)
#define LOG2E 1.4426950408889634f
#define EOFF 8.0f                // e = 2^(s*log2e - EOFF); cancels in o/l

// Scratch
__device__ __half g_qkv[(size_t)M_TOTAL * QKV_N];   // Q pre-scaled
__device__ __half g_o[(size_t)M_TOTAL * D];

// ---- helpers --------------------------------------------------------------
__device__ __forceinline__ uint32_t smem_u32(const void* p) {
    return (uint32_t)__cvta_generic_to_shared(p);
}
__device__ __forceinline__ void ldmx4(uint32_t* r, uint32_t a) {
    asm volatile("ldmatrix.sync.aligned.m8n8.x4.shared.b16 {%0,%1,%2,%3}, [%4];"
                 : "=r"(r[0]), "=r"(r[1]), "=r"(r[2]), "=r"(r[3]) : "r"(a));
}
__device__ __forceinline__ void ldmx4t(uint32_t* r, uint32_t a) {
    asm volatile("ldmatrix.sync.aligned.m8n8.x4.trans.shared.b16 {%0,%1,%2,%3}, [%4];"
                 : "=r"(r[0]), "=r"(r[1]), "=r"(r[2]), "=r"(r[3]) : "r"(a));
}
__device__ __forceinline__ void mma16816(float* d, const uint32_t* a, const uint32_t* b) {
    asm volatile(
        "mma.sync.aligned.m16n8k16.row.col.f32.f16.f16.f32 "
        "{%0,%1,%2,%3}, {%4,%5,%6,%7}, {%8,%9}, {%0,%1,%2,%3};"
        : "+f"(d[0]), "+f"(d[1]), "+f"(d[2]), "+f"(d[3])
        : "r"(a[0]), "r"(a[1]), "r"(a[2]), "r"(a[3]), "r"(b[0]), "r"(b[1]));
}
__device__ __forceinline__ uint32_t packh2(float x, float y) {
    __half2 t = __floats2half2_rn(x, y);
    return *(uint32_t*)&t;
}
__device__ __forceinline__ uint32_t ex2h2(uint32_t p) {
    uint32_t e;
    asm("ex2.approx.f16x2 %0, %1;" : "=r"(e) : "r"(p));
    return e;
}

// ---------------------------------------------------------------------------
// QKV kernel: grid (3, 512) = (n-chunk, m-tile). 256 threads, 2x4 warps,
// warp tile 64x32. LN fused into A-staging (recomputed per n-chunk).
// smem 64 KB: As[128][128] + Bs[128][128] fp16, swizzled
// (16B chunk c (0..15) in a 256B row -> c ^ (row & 7)).
// Output g_qkv fp16, Q columns (chunk 0) pre-scaled by 1/sqrt(hd).
// ---------------------------------------------------------------------------
__global__ __launch_bounds__(256, 2)
void qkv_kernel(const float* __restrict__ z,
                const float* __restrict__ lng,
                const float* __restrict__ lnb,
                const float* __restrict__ wq,
                const float* __restrict__ bias) {
    extern __shared__ char sm_raw[];
    __half* As = (__half*)sm_raw;            // 128x128
    __half* Bs = As + 128 * 128;

    int tid = threadIdx.x;
    int nc0 = blockIdx.x;                    // 0..2
    int m0 = blockIdx.y * 128;

    // ---- LN + stage A: 2 threads per row (each half = 64 dims) ----
    {
        int row = tid >> 1, hf = tid & 1;
        const float4* zp = (const float4*)(z + (size_t)(m0 + row) * D + hf * 64);
        float s0 = 0.0f, s1 = 0.0f;
        #pragma unroll
        for (int j = 0; j < 16; j++) {
            float4 t = zp[j];
            s0 += t.x + t.y + t.z + t.w;
            s1 += t.x * t.x + t.y * t.y + t.z * t.z + t.w * t.w;
        }
        s0 += __shfl_xor_sync(0xffffffffu, s0, 1);
        s1 += __shfl_xor_sync(0xffffffffu, s1, 1);
        float mu = s0 * (1.0f / 128.0f);
        float var = s1 * (1.0f / 128.0f) - mu * mu;
        float rstd = rsqrtf(var + 1e-5f);

        const float4* gp = (const float4*)(lng + hf * 64);
        const float4* bp = (const float4*)(lnb + hf * 64);
        #pragma unroll
        for (int j = 0; j < 16; j++) {
            float4 t = zp[j];
            float4 gg = gp[j];
            float4 bb = bp[j];
            uint2 o2;
            o2.x = packh2((t.x - mu) * rstd * gg.x + bb.x,
                          (t.y - mu) * rstd * gg.y + bb.y);
            o2.y = packh2((t.z - mu) * rstd * gg.z + bb.z,
                          (t.w - mu) * rstd * gg.w + bb.w);
            int c = (hf * 64 + j * 4) >> 3;       // 16B chunk
            int sub = j & 1;
            *(uint2*)&As[row * 128 + ((c ^ (row & 7)) * 8) + sub * 4] = o2;
        }
    }

    // ---- stage B chunk (128 k x 128 n) from fp32 with cast ----
    #pragma unroll
    for (int i = 0; i < 16; i++) {
        int idx = tid + i * 256;              // 4096 float4-groups
        int k = idx >> 5, g4 = idx & 31;
        float4 t = *(const float4*)&wq[(size_t)k * QKV_N + nc0 * 128 + g4 * 4];
        uint2 o2;
        o2.x = packh2(t.x, t.y);
        o2.y = packh2(t.z, t.w);
        int cc = g4 >> 1, sub = g4 & 1;
        *(uint2*)&Bs[k * 128 + ((cc ^ (k & 7)) * 8) + sub * 4] = o2;
    }
    __syncthreads();

    int w = tid >> 5, l = tid & 31;
    int mw = (w >> 2) * 64, nw = (w & 3) * 32;
    int sel = l >> 3, li = l & 7;
    int grp = l >> 2, qd = l & 3;

    uint32_t Abase = smem_u32(As);
    uint32_t Bbase = smem_u32(Bs);

    float acc[4][4][4];
    #pragma unroll
    for (int mt = 0; mt < 4; mt++)
        #pragma unroll
        for (int nt = 0; nt < 4; nt++)
            #pragma unroll
            for (int j = 0; j < 4; j++) acc[mt][nt][j] = 0.0f;

    #pragma unroll
    for (int kt = 0; kt < 8; kt++) {
        uint32_t af[4][4];
        #pragma unroll
        for (int mt = 0; mt < 4; mt++) {
            int m = mw + mt * 16 + li + ((sel & 1) << 3);
            int kc = kt * 2 + (sel >> 1);
            ldmx4(af[mt], Abase + (uint32_t)(m * 128 + ((kc ^ (m & 7)) * 8)) * 2);
        }
        uint32_t bf_[4][2];
        #pragma unroll
        for (int p = 0; p < 2; p++) {
            int k = kt * 16 + ((sel & 1) << 3) + li;
            int ncc = (nw >> 3) + p * 2 + (sel >> 1);
            uint32_t t[4];
            ldmx4t(t, Bbase + (uint32_t)(k * 128 + ((ncc ^ (k & 7)) * 8)) * 2);
            bf_[2 * p][0] = t[0]; bf_[2 * p][1] = t[1];
            bf_[2 * p + 1][0] = t[2]; bf_[2 * p + 1][1] = t[3];
        }
        #pragma unroll
        for (int mt = 0; mt < 4; mt++)
            #pragma unroll
            for (int nt = 0; nt < 4; nt++)
                mma16816(acc[mt][nt], af[mt], bf_[nt]);
    }

    // ---- epilogue ----
    float sc = (nc0 == 0) ? QSCALE : 1.0f;
    #pragma unroll
    for (int mt = 0; mt < 4; mt++) {
        #pragma unroll
        for (int nt = 0; nt < 4; nt++) {
            int gm = m0 + mw + mt * 16 + grp;
            int gn = nc0 * 128 + nw + nt * 8 + qd * 2;
            float b0 = bias[gn], b1 = bias[gn + 1];
            float v0 = (acc[mt][nt][0] + b0) * sc;
            float v1 = (acc[mt][nt][1] + b1) * sc;
            float v2 = (acc[mt][nt][2] + b0) * sc;
            float v3 = (acc[mt][nt][3] + b1) * sc;
            *(uint32_t*)&g_qkv[(size_t)gm * QKV_N + gn] = packh2(v0, v1);
            *(uint32_t*)&g_qkv[(size_t)(gm + 8) * QKV_N + gn] = packh2(v2, v3);
        }
    }
}

// ---------------------------------------------------------------------------
// Proj kernel: out = g_o @ Wp + b + z. grid 512, 256 threads, smem 64 KB.
// ---------------------------------------------------------------------------
__global__ __launch_bounds__(256, 2)
void proj_kernel(const float* __restrict__ wp,
                 const float* __restrict__ bias,
                 const float* __restrict__ Zr,
                 float* __restrict__ Cout) {
    extern __shared__ char sm_raw[];
    __half* As = (__half*)sm_raw;
    __half* Bs = As + 128 * 128;

    int tid = threadIdx.x;
    int m0 = blockIdx.x * 128;

    #pragma unroll
    for (int i = 0; i < 8; i++) {
        int idx = tid + i * 256;
        int m = idx >> 4, c = idx & 15;
        *(uint4*)&As[m * 128 + ((c ^ (m & 7)) * 8)] =
            *(const uint4*)&g_o[(size_t)(m0 + m) * D + c * 8];
    }
    #pragma unroll
    for (int i = 0; i < 16; i++) {
        int idx = tid + i * 256;
        int k = idx >> 5, g4 = idx & 31;
        float4 t = *(const float4*)&wp[(size_t)k * D + g4 * 4];
        uint2 o2;
        o2.x = packh2(t.x, t.y);
        o2.y = packh2(t.z, t.w);
        int cc = g4 >> 1, sub = g4 & 1;
        *(uint2*)&Bs[k * 128 + ((cc ^ (k & 7)) * 8) + sub * 4] = o2;
    }
    __syncthreads();

    int w = tid >> 5, l = tid & 31;
    int mw = (w >> 2) * 64, nw = (w & 3) * 32;
    int sel = l >> 3, li = l & 7;

    uint32_t Abase = smem_u32(As);
    uint32_t Bbase = smem_u32(Bs);

    float acc[4][4][4];
    #pragma unroll
    for (int mt = 0; mt < 4; mt++)
        #pragma unroll
        for (int nt = 0; nt < 4; nt++)
            #pragma unroll
            for (int j = 0; j < 4; j++) acc[mt][nt][j] = 0.0f;

    #pragma unroll
    for (int kt = 0; kt < 8; kt++) {
        uint32_t af[4][4];
        #pragma unroll
        for (int mt = 0; mt < 4; mt++) {
            int m = mw + mt * 16 + li + ((sel & 1) << 3);
            int kc = kt * 2 + (sel >> 1);
            ldmx4(af[mt], Abase + (uint32_t)(m * 128 + ((kc ^ (m & 7)) * 8)) * 2);
        }
        uint32_t bf_[4][2];
        #pragma unroll
        for (int p = 0; p < 2; p++) {
            int k = kt * 16 + ((sel & 1) << 3) + li;
            int ncc = (nw >> 3) + p * 2 + (sel >> 1);
            uint32_t t[4];
            ldmx4t(t, Bbase + (uint32_t)(k * 128 + ((ncc ^ (k & 7)) * 8)) * 2);
            bf_[2 * p][0] = t[0]; bf_[2 * p][1] = t[1];
            bf_[2 * p + 1][0] = t[2]; bf_[2 * p + 1][1] = t[3];
        }
        #pragma unroll
        for (int mt = 0; mt < 4; mt++)
            #pragma unroll
            for (int nt = 0; nt < 4; nt++)
                mma16816(acc[mt][nt], af[mt], bf_[nt]);
    }

    int grp = l >> 2, qd = l & 3;
    #pragma unroll
    for (int mt = 0; mt < 4; mt++) {
        #pragma unroll
        for (int nt = 0; nt < 4; nt++) {
            int gm = m0 + mw + mt * 16 + grp;
            int gn = nw + nt * 8 + qd * 2;
            float b0 = bias[gn], b1 = bias[gn + 1];
            float2 r0 = *(const float2*)&Zr[(size_t)gm * D + gn];
            float2 r1 = *(const float2*)&Zr[(size_t)(gm + 8) * D + gn];
            *(float2*)&Cout[(size_t)gm * D + gn] =
                make_float2(acc[mt][nt][0] + b0 + r0.x, acc[mt][nt][1] + b1 + r0.y);
            *(float2*)&Cout[(size_t)(gm + 8) * D + gn] =
                make_float2(acc[mt][nt][2] + b0 + r1.x, acc[mt][nt][3] + b1 + r1.y);
        }
    }
}

// ---------------------------------------------------------------------------
// Attention: block per (h, r), 256 threads = 8 warps x 32 queries.
// Offset softmax (e = 2^(s*log2e - 8)), K-fragment double buffer.
// smem: Q/K/V [256][pitch 40 halves] (80B rows, conflict-free). 60 KB.
// ---------------------------------------------------------------------------
#define APITCH 40

__device__ __forceinline__ void load_kf(uint32_t Kbase, int t, int sel, int li,
                                        uint32_t kf[2][4][2]) {
    #pragma unroll
    for (int kk = 0; kk < 2; kk++)
        #pragma unroll
        for (int p = 0; p < 2; p++) {
            int key = t * 32 + p * 16 + ((sel >> 1) << 3) + li;
            int dc = kk * 2 + (sel & 1);
            uint32_t tr[4];
            ldmx4(tr, Kbase + (uint32_t)(key * APITCH + dc * 8) * 2);
            kf[kk][2 * p][0] = tr[0]; kf[kk][2 * p][1] = tr[1];
            kf[kk][2 * p + 1][0] = tr[2]; kf[kk][2 * p + 1][1] = tr[3];
        }
}

__global__ __launch_bounds__(256, 2)
void attn_kernel() {
    extern __shared__ char sm_raw[];
    __half* Qs = (__half*)sm_raw;            // 256 * 40
    __half* Ks = Qs + 256 * APITCH;
    __half* Vs = Ks + 256 * APITCH;

    int h = blockIdx.x;
    int r = blockIdx.y;
    int tid = threadIdx.x;
    size_t mbase = (size_t)r * L;

    #pragma unroll
    for (int mat = 0; mat < 3; mat++) {
        __half* dst = (mat == 0) ? Qs : (mat == 1) ? Ks : Vs;
        int col0 = mat * D + h * HD;
        #pragma unroll
        for (int i = 0; i < 4; i++) {
            int idx = tid + i * 256;
            int pos = idx >> 2, c = idx & 3;
            *(uint4*)&dst[pos * APITCH + c * 8] =
                *(const uint4*)&g_qkv[(mbase + pos) * QKV_N + col0 + c * 8];
        }
    }
    __syncthreads();

    int w = tid >> 5, l = tid & 31;
    int q0 = w * 32;
    int sel = l >> 3, li = l & 7, grp = l >> 2, qd = l & 3;

    uint32_t Qbase = smem_u32(Qs);
    uint32_t Kbase = smem_u32(Ks);
    uint32_t Vbase = smem_u32(Vs);

    uint32_t qf[2][2][4];
    #pragma unroll
    for (int kk = 0; kk < 2; kk++)
        #pragma unroll
        for (int mt = 0; mt < 2; mt++) {
            int m = q0 + mt * 16 + li + ((sel & 1) << 3);
            int kc = kk * 2 + (sel >> 1);
            ldmx4(qf[kk][mt], Qbase + (uint32_t)(m * APITCH + kc * 8) * 2);
        }

    float lacc[2][2] = {{0.0f, 0.0f}, {0.0f, 0.0f}};
    float o[2][4][4];
    #pragma unroll
    for (int mt = 0; mt < 2; mt++)
        #pragma unroll
        for (int nt = 0; nt < 4; nt++)
            #pragma unroll
            for (int j = 0; j < 4; j++) o[mt][nt][j] = 0.0f;

    uint32_t kfA[2][4][2], kfB[2][4][2];
    load_kf(Kbase, 0, sel, li, kfA);

// One key-tile body: S-MMA from KCUR, prefetch next tile into KNXT, softmax, PV.
#define ATTN_TILE(T, KCUR, KNXT)                                               \
    {                                                                          \
        const int t = (T);                                                     \
        float s[2][4][4];                                                      \
        _Pragma("unroll")                                                      \
        for (int mt = 0; mt < 2; mt++)                                         \
            _Pragma("unroll")                                                  \
            for (int nt = 0; nt < 4; nt++)                                     \
                _Pragma("unroll")                                              \
                for (int j = 0; j < 4; j++) s[mt][nt][j] = 0.0f;               \
        _Pragma("unroll")                                                      \
        for (int kk = 0; kk < 2; kk++)                                         \
            _Pragma("unroll")                                                  \
            for (int mt = 0; mt < 2; mt++)                                     \
                _Pragma("unroll")                                              \
                for (int nt = 0; nt < 4; nt++)                                 \
                    mma16816(s[mt][nt], qf[kk][mt], KCUR[kk][nt]);             \
        if (t < 7) load_kf(Kbase, t + 1, sel, li, KNXT);                       \
        uint32_t pe[2][4][2];                                                  \
        _Pragma("unroll")                                                      \
        for (int mt = 0; mt < 2; mt++)                                         \
            _Pragma("unroll")                                                  \
            for (int nt = 0; nt < 4; nt++)                                     \
                _Pragma("unroll")                                              \
                for (int hf = 0; hf < 2; hf++) {                               \
                    float x0 = s[mt][nt][2 * hf] * LOG2E - EOFF;               \
                    float x1 = s[mt][nt][2 * hf + 1] * LOG2E - EOFF;           \
                    pe[mt][nt][hf] = ex2h2(packh2(x0, x1));                    \
                }                                                              \
        _Pragma("unroll")                                                      \
        for (int mt = 0; mt < 2; mt++)                                         \
            _Pragma("unroll")                                                  \
            for (int hf = 0; hf < 2; hf++) {                                   \
                __half2 a = *(__half2*)&pe[mt][0][hf];                         \
                __half2 b = *(__half2*)&pe[mt][1][hf];                         \
                __half2 c = *(__half2*)&pe[mt][2][hf];                         \
                __half2 d = *(__half2*)&pe[mt][3][hf];                         \
                __half2 sum = __hadd2(__hadd2(a, b), __hadd2(c, d));           \
                float2 f = __half22float2(sum);                                \
                lacc[mt][hf] += f.x + f.y;                                     \
            }                                                                  \
        _Pragma("unroll")                                                      \
        for (int kt = 0; kt < 2; kt++) {                                       \
            uint32_t pa[2][4];                                                 \
            _Pragma("unroll")                                                  \
            for (int mt = 0; mt < 2; mt++)                                     \
                _Pragma("unroll")                                              \
                for (int j = 0; j < 4; j++)                                    \
                    pa[mt][j] = pe[mt][2 * kt + (j >> 1)][j & 1];              \
            uint32_t vf[4][2];                                                 \
            _Pragma("unroll")                                                  \
            for (int p = 0; p < 2; p++) {                                      \
                int key = t * 32 + kt * 16 + ((sel & 1) << 3) + li;            \
                int dc = p * 2 + (sel >> 1);                                   \
                uint32_t tr[4];                                                \
                ldmx4t(tr, Vbase + (uint32_t)(key * APITCH + dc * 8) * 2);     \
                vf[2 * p][0] = tr[0]; vf[2 * p][1] = tr[1];                    \
                vf[2 * p + 1][0] = tr[2]; vf[2 * p + 1][1] = tr[3];            \
            }                                                                  \
            _Pragma("unroll")                                                  \
            for (int mt = 0; mt < 2; mt++)                                     \
                _Pragma("unroll")                                              \
                for (int nt = 0; nt < 4; nt++)                                 \
                    mma16816(o[mt][nt], pa[mt], vf[nt]);                       \
        }                                                                      \
    }

    #pragma unroll 1
    for (int tt = 0; tt < 4; tt++) {
        ATTN_TILE(2 * tt,     kfA, kfB)
        ATTN_TILE(2 * tt + 1, kfB, kfA)
    }
#undef ATTN_TILE

    #pragma unroll
    for (int mt = 0; mt < 2; mt++)
        #pragma unroll
        for (int hf = 0; hf < 2; hf++) {
            float v = lacc[mt][hf];
            v += __shfl_xor_sync(0xffffffffu, v, 1);
            v += __shfl_xor_sync(0xffffffffu, v, 2);
            lacc[mt][hf] = v;
        }

    #pragma unroll
    for (int mt = 0; mt < 2; mt++) {
        float inv0 = 1.0f / lacc[mt][0];
        float inv1 = 1.0f / lacc[mt][1];
        #pragma unroll
        for (int nt = 0; nt < 4; nt++) {
            int q = q0 + mt * 16 + grp;
            int d = nt * 8 + qd * 2;
            size_t off0 = (mbase + q) * D + h * HD + d;
            size_t off1 = (mbase + q + 8) * D + h * HD + d;
            *(uint32_t*)&g_o[off0] = packh2(o[mt][nt][0] * inv0, o[mt][nt][1] * inv0);
            *(uint32_t*)&g_o[off1] = packh2(o[mt][nt][2] * inv1, o[mt][nt][3] * inv1);
        }
    }
}

// ---------------------------------------------------------------------------
// Launch
// ---------------------------------------------------------------------------
extern "C" void kernel_launch(void* const* d_in, const int* in_sizes, int n_in,
                              void* d_out, int out_size) {
    const float* z      = (const float*)d_in[0];
    const float* ln_g   = (const float*)d_in[1];
    const float* ln_b   = (const float*)d_in[2];
    const float* w_qkv  = (const float*)d_in[3];
    const float* b_qkv  = (const float*)d_in[4];
    const float* w_proj = (const float*)d_in[5];
    const float* b_proj = (const float*)d_in[6];
    float* out = (float*)d_out;

    const int GEMM_SMEM = 2 * 128 * 128 * 2;       // 65536 B
    const int ATTN_SMEM = 3 * 256 * APITCH * 2;    // 61440 B
    cudaFuncSetAttribute(qkv_kernel,
                         cudaFuncAttributeMaxDynamicSharedMemorySize, GEMM_SMEM);
    cudaFuncSetAttribute(proj_kernel,
                         cudaFuncAttributeMaxDynamicSharedMemorySize, GEMM_SMEM);
    cudaFuncSetAttribute(attn_kernel,
                         cudaFuncAttributeMaxDynamicSharedMemorySize, ATTN_SMEM);

    qkv_kernel<<<dim3(3, M_TOTAL / 128), 256, GEMM_SMEM>>>(z, ln_g, ln_b, w_qkv, b_qkv);
    attn_kernel<<<dim3(NH, L), 256, ATTN_SMEM>>>();
    proj_kernel<<<M_TOTAL / 128, 256, GEMM_SMEM>>>(w_proj, b_proj, z, out);
}

// round 14
// speedup vs baseline: 1.3655x; 1.3655x over previous
#include <cuda_runtime.h>
#include <cuda_fp16.h>
#include <math.h>
#include <stdint.h>

// ---------------------------------------------------------------------------
// PairwiseAttention round 11: consolidation on the measured-best round-7
// structure (separate LN, fp16 single-pass GEMMs, offset-softmax attn).
// Deltas vs round 7: (1) ln+castw merged into one launch (grid branch),
// (2) attn V-fragment loads hoisted before the exp chain (+8 regs, <128).
// Reverted: LN-in-staging fusion (L1-bound regression, rounds 9/10) and
// attn K double-buffer (register spill regression).
// ---------------------------------------------------------------------------

#define L 256
#define D 128
#define NH 4
#define HD 32
#define M_TOTAL (L * L)          // 65536
#define QKV_N (3 * D)            // 384
#define QSCALE 0.17677669529663687f   // 1/sqrt(32)
#define LOG2E 1.4426950408889634f
#define EOFF 8.0f                // e = 2^(s*log2e - EOFF); cancels in o/l

// Scratch
__device__ __half g_zn[(size_t)M_TOTAL * D];
__device__ __half g_qkv[(size_t)M_TOTAL * QKV_N];   // Q pre-scaled
__device__ __half g_o[(size_t)M_TOTAL * D];
__device__ __half g_wq[D * QKV_N];
__device__ __half g_wp[D * D];

// ---- helpers --------------------------------------------------------------
__device__ __forceinline__ uint32_t smem_u32(const void* p) {
    return (uint32_t)__cvta_generic_to_shared(p);
}
__device__ __forceinline__ void ldmx4(uint32_t* r, uint32_t a) {
    asm volatile("ldmatrix.sync.aligned.m8n8.x4.shared.b16 {%0,%1,%2,%3}, [%4];"
                 : "=r"(r[0]), "=r"(r[1]), "=r"(r[2]), "=r"(r[3]) : "r"(a));
}
__device__ __forceinline__ void ldmx4t(uint32_t* r, uint32_t a) {
    asm volatile("ldmatrix.sync.aligned.m8n8.x4.trans.shared.b16 {%0,%1,%2,%3}, [%4];"
                 : "=r"(r[0]), "=r"(r[1]), "=r"(r[2]), "=r"(r[3]) : "r"(a));
}
__device__ __forceinline__ void mma16816(float* d, const uint32_t* a, const uint32_t* b) {
    asm volatile(
        "mma.sync.aligned.m16n8k16.row.col.f32.f16.f16.f32 "
        "{%0,%1,%2,%3}, {%4,%5,%6,%7}, {%8,%9}, {%0,%1,%2,%3};"
        : "+f"(d[0]), "+f"(d[1]), "+f"(d[2]), "+f"(d[3])
        : "r"(a[0]), "r"(a[1]), "r"(a[2]), "r"(a[3]), "r"(b[0]), "r"(b[1]));
}
__device__ __forceinline__ uint32_t packh2(float x, float y) {
    __half2 t = __floats2half2_rn(x, y);
    return *(uint32_t*)&t;
}
__device__ __forceinline__ uint32_t ex2h2(uint32_t p) {
    uint32_t e;
    asm("ex2.approx.f16x2 %0, %1;" : "=r"(e) : "r"(p));
    return e;
}

// ---------------------------------------------------------------------------
// Merged LN + weight-cast kernel. Blocks [0, 8192): LN (one warp per
// position, 8 positions/block). Blocks [8192, 8448): cast wq/wp to fp16.
// ---------------------------------------------------------------------------
#define LN_BLOCKS (M_TOTAL / 8)
#define CAST_BLOCKS ((D * QKV_N + D * D + 255) / 256)

__global__ void ln_cast_kernel(const float* __restrict__ z,
                               const float* __restrict__ g,
                               const float* __restrict__ b,
                               const float* __restrict__ wq,
                               const float* __restrict__ wp) {
    int bid = blockIdx.x;
    if (bid < LN_BLOCKS) {
        int pos  = bid * 8 + (threadIdx.x >> 5);
        int lane = threadIdx.x & 31;
        const float* zp = z + (size_t)pos * D;

        float4 v = *(const float4*)&zp[lane * 4];
        float s = v.x + v.y + v.z + v.w;
        #pragma unroll
        for (int o = 16; o; o >>= 1) s += __shfl_xor_sync(0xffffffffu, s, o);
        float mu = s * (1.0f / 128.0f);

        float dx = v.x - mu, dy = v.y - mu, dz = v.z - mu, dw = v.w - mu;
        float q = dx * dx + dy * dy + dz * dz + dw * dw;
        #pragma unroll
        for (int o = 16; o; o >>= 1) q += __shfl_xor_sync(0xffffffffu, q, o);
        float rstd = rsqrtf(q * (1.0f / 128.0f) + 1e-5f);

        float4 gg = *(const float4*)&g[lane * 4];
        float4 bb = *(const float4*)&b[lane * 4];
        uint2 o2;
        o2.x = packh2(dx * rstd * gg.x + bb.x, dy * rstd * gg.y + bb.y);
        o2.y = packh2(dz * rstd * gg.z + bb.z, dw * rstd * gg.w + bb.w);
        *(uint2*)&g_zn[(size_t)pos * D + lane * 4] = o2;
    } else {
        int i = (bid - LN_BLOCKS) * 256 + threadIdx.x;
        if (i < D * QKV_N) g_wq[i] = __float2half_rn(wq[i]);
        else {
            int j = i - D * QKV_N;
            if (j < D * D) g_wp[j] = __float2half_rn(wp[j]);
        }
    }
}

// ---------------------------------------------------------------------------
// GEMM: C[M x N] = A[M x 128] @ W[128 x N] (single fp16 pass).
// Block 128x128, 256 threads (2x4 warps, 64x32 warp tile). smem 64 KB.
// Rows 256B = 16 chunks of 16B, swizzle chunk c -> c ^ (row & 7).
// MODE 0: A=g_zn, W=g_wq, C=g_qkv fp16 (+bias, Q cols pre-scaled), N=384
// MODE 1: A=g_o,  W=g_wp, C=out fp32 (+bias +z residual), N=128
// ---------------------------------------------------------------------------
template<int MODE>
__global__ __launch_bounds__(256, 2)
void gemm_kernel(const float* __restrict__ bias,
                 const float* __restrict__ Zr,
                 float* __restrict__ Cout) {
    constexpr int N = (MODE == 0) ? QKV_N : D;
    extern __shared__ char sm_raw[];
    __half* As = (__half*)sm_raw;            // 128x128
    __half* Bs = As + 128 * 128;

    int tid = threadIdx.x;
    int m0 = blockIdx.y * 128;
    int n0 = blockIdx.x * 128;

    const __half* Ag = (MODE == 0) ? g_zn : g_o;
    const __half* Bg = (MODE == 0) ? g_wq : g_wp;

    #pragma unroll
    for (int i = 0; i < 8; i++) {
        int idx = tid + i * 256;
        int m = idx >> 4, c = idx & 15;
        *(uint4*)&As[m * 128 + ((c ^ (m & 7)) * 8)] =
            *(const uint4*)&Ag[(size_t)(m0 + m) * D + c * 8];
    }
    #pragma unroll
    for (int i = 0; i < 8; i++) {
        int idx = tid + i * 256;
        int k = idx >> 4, c = idx & 15;
        *(uint4*)&Bs[k * 128 + ((c ^ (k & 7)) * 8)] =
            *(const uint4*)&Bg[(size_t)k * N + n0 + c * 8];
    }
    __syncthreads();

    int w = tid >> 5, l = tid & 31;
    int mw = (w >> 2) * 64, nw = (w & 3) * 32;
    int sel = l >> 3, li = l & 7;

    uint32_t Abase = smem_u32(As);
    uint32_t Bbase = smem_u32(Bs);

    float acc[4][4][4];
    #pragma unroll
    for (int mt = 0; mt < 4; mt++)
        #pragma unroll
        for (int nt = 0; nt < 4; nt++)
            #pragma unroll
            for (int j = 0; j < 4; j++) acc[mt][nt][j] = 0.0f;

    #pragma unroll
    for (int kt = 0; kt < 8; kt++) {
        uint32_t af[4][4];
        #pragma unroll
        for (int mt = 0; mt < 4; mt++) {
            int m = mw + mt * 16 + li + ((sel & 1) << 3);
            int kc = kt * 2 + (sel >> 1);
            ldmx4(af[mt], Abase + (uint32_t)(m * 128 + ((kc ^ (m & 7)) * 8)) * 2);
        }
        uint32_t bf_[4][2];
        #pragma unroll
        for (int p = 0; p < 2; p++) {
            int k = kt * 16 + ((sel & 1) << 3) + li;
            int nc = (nw >> 3) + p * 2 + (sel >> 1);
            uint32_t t[4];
            ldmx4t(t, Bbase + (uint32_t)(k * 128 + ((nc ^ (k & 7)) * 8)) * 2);
            bf_[2 * p][0] = t[0]; bf_[2 * p][1] = t[1];
            bf_[2 * p + 1][0] = t[2]; bf_[2 * p + 1][1] = t[3];
        }
        #pragma unroll
        for (int mt = 0; mt < 4; mt++)
            #pragma unroll
            for (int nt = 0; nt < 4; nt++)
                mma16816(acc[mt][nt], af[mt], bf_[nt]);
    }

    int grp = l >> 2, qd = l & 3;
    #pragma unroll
    for (int mt = 0; mt < 4; mt++) {
        #pragma unroll
        for (int nt = 0; nt < 4; nt++) {
            int gm = m0 + mw + mt * 16 + grp;
            int gn = n0 + nw + nt * 8 + qd * 2;
            float b0 = bias[gn], b1 = bias[gn + 1];
            float v0 = acc[mt][nt][0] + b0;
            float v1 = acc[mt][nt][1] + b1;
            float v2 = acc[mt][nt][2] + b0;
            float v3 = acc[mt][nt][3] + b1;
            if (MODE == 0) {
                float sc = (gn < D) ? QSCALE : 1.0f;
                *(uint32_t*)&g_qkv[(size_t)gm * N + gn] = packh2(v0 * sc, v1 * sc);
                *(uint32_t*)&g_qkv[(size_t)(gm + 8) * N + gn] = packh2(v2 * sc, v3 * sc);
            } else {
                float2 r0 = *(const float2*)&Zr[(size_t)gm * N + gn];
                float2 r1 = *(const float2*)&Zr[(size_t)(gm + 8) * N + gn];
                *(float2*)&Cout[(size_t)gm * N + gn] = make_float2(v0 + r0.x, v1 + r0.y);
                *(float2*)&Cout[(size_t)(gm + 8) * N + gn] = make_float2(v2 + r1.x, v3 + r1.y);
            }
        }
    }
}

// ---------------------------------------------------------------------------
// Attention: block per (h, r), 256 threads = 8 warps x 32 queries.
// Offset softmax: e = 2^(s*log2e - 8), no max tracking, no rescaling.
// V-fragment loads for BOTH k16 halves hoisted before the exp chain so
// LDS latency hides under the MUFU/FMA softmax work.
// smem: Q/K/V [256][pitch 40 halves] (80B rows, conflict-free). 60 KB.
// ---------------------------------------------------------------------------
#define APITCH 40
__global__ __launch_bounds__(256, 2)
void attn_kernel() {
    extern __shared__ char sm_raw[];
    __half* Qs = (__half*)sm_raw;            // 256 * 40
    __half* Ks = Qs + 256 * APITCH;
    __half* Vs = Ks + 256 * APITCH;

    int h = blockIdx.x;
    int r = blockIdx.y;
    int tid = threadIdx.x;
    size_t mbase = (size_t)r * L;

    #pragma unroll
    for (int mat = 0; mat < 3; mat++) {
        __half* dst = (mat == 0) ? Qs : (mat == 1) ? Ks : Vs;
        int col0 = mat * D + h * HD;
        #pragma unroll
        for (int i = 0; i < 4; i++) {
            int idx = tid + i * 256;
            int pos = idx >> 2, c = idx & 3;
            *(uint4*)&dst[pos * APITCH + c * 8] =
                *(const uint4*)&g_qkv[(mbase + pos) * QKV_N + col0 + c * 8];
        }
    }
    __syncthreads();

    int w = tid >> 5, l = tid & 31;
    int q0 = w * 32;
    int sel = l >> 3, li = l & 7, grp = l >> 2, qd = l & 3;

    uint32_t Qbase = smem_u32(Qs);
    uint32_t Kbase = smem_u32(Ks);
    uint32_t Vbase = smem_u32(Vs);

    uint32_t qf[2][2][4];
    #pragma unroll
    for (int kk = 0; kk < 2; kk++)
        #pragma unroll
        for (int mt = 0; mt < 2; mt++) {
            int m = q0 + mt * 16 + li + ((sel & 1) << 3);
            int kc = kk * 2 + (sel >> 1);
            ldmx4(qf[kk][mt], Qbase + (uint32_t)(m * APITCH + kc * 8) * 2);
        }

    float lacc[2][2] = {{0.0f, 0.0f}, {0.0f, 0.0f}};   // [mt][row-half]
    float o[2][4][4];
    #pragma unroll
    for (int mt = 0; mt < 2; mt++)
        #pragma unroll
        for (int nt = 0; nt < 4; nt++)
            #pragma unroll
            for (int j = 0; j < 4; j++) o[mt][nt][j] = 0.0f;

    #pragma unroll 1
    for (int t = 0; t < 8; t++) {             // key tiles of 32
        // ---- S = Q K^T (32 x 32) ----
        float s[2][4][4];
        #pragma unroll
        for (int mt = 0; mt < 2; mt++)
            #pragma unroll
            for (int nt = 0; nt < 4; nt++)
                #pragma unroll
                for (int j = 0; j < 4; j++) s[mt][nt][j] = 0.0f;

        #pragma unroll
        for (int kk = 0; kk < 2; kk++) {
            uint32_t kf[4][2];
            #pragma unroll
            for (int p = 0; p < 2; p++) {
                int key = t * 32 + p * 16 + ((sel >> 1) << 3) + li;
                int dc = kk * 2 + (sel & 1);
                uint32_t tr[4];
                ldmx4(tr, Kbase + (uint32_t)(key * APITCH + dc * 8) * 2);
                kf[2 * p][0] = tr[0]; kf[2 * p][1] = tr[1];
                kf[2 * p + 1][0] = tr[2]; kf[2 * p + 1][1] = tr[3];
            }
            #pragma unroll
            for (int mt = 0; mt < 2; mt++)
                #pragma unroll
                for (int nt = 0; nt < 4; nt++)
                    mma16816(s[mt][nt], qf[kk][mt], kf[nt]);
        }

        // ---- V fragments for both k16 halves, loaded EARLY so the LDS
        //      latency hides under the exp/pack chain below ----
        uint32_t vf[2][4][2];
        #pragma unroll
        for (int kt = 0; kt < 2; kt++)
            #pragma unroll
            for (int p = 0; p < 2; p++) {
                int key = t * 32 + kt * 16 + ((sel & 1) << 3) + li;
                int dc = p * 2 + (sel >> 1);
                uint32_t tr[4];
                ldmx4t(tr, Vbase + (uint32_t)(key * APITCH + dc * 8) * 2);
                vf[kt][2 * p][0] = tr[0]; vf[kt][2 * p][1] = tr[1];
                vf[kt][2 * p + 1][0] = tr[2]; vf[kt][2 * p + 1][1] = tr[3];
            }

        // ---- P = exp(S) * 2^-EOFF, in fp16 pairs ----
        uint32_t pe[2][4][2];     // [mt][nt][row-half]
        #pragma unroll
        for (int mt = 0; mt < 2; mt++)
            #pragma unroll
            for (int nt = 0; nt < 4; nt++)
                #pragma unroll
                for (int hf = 0; hf < 2; hf++) {
                    float x0 = s[mt][nt][2 * hf] * LOG2E - EOFF;
                    float x1 = s[mt][nt][2 * hf + 1] * LOG2E - EOFF;
                    pe[mt][nt][hf] = ex2h2(packh2(x0, x1));
                }

        // ---- l partial sums (fp16 tree of 4, then fp32 accumulate) ----
        #pragma unroll
        for (int mt = 0; mt < 2; mt++)
            #pragma unroll
            for (int hf = 0; hf < 2; hf++) {
                __half2 a = *(__half2*)&pe[mt][0][hf];
                __half2 b = *(__half2*)&pe[mt][1][hf];
                __half2 c = *(__half2*)&pe[mt][2][hf];
                __half2 d = *(__half2*)&pe[mt][3][hf];
                __half2 sum = __hadd2(__hadd2(a, b), __hadd2(c, d));
                float2 f = __half22float2(sum);
                lacc[mt][hf] += f.x + f.y;
            }

        // ---- O += P V ----
        #pragma unroll
        for (int kt = 0; kt < 2; kt++) {
            uint32_t pa[2][4];
            #pragma unroll
            for (int mt = 0; mt < 2; mt++)
                #pragma unroll
                for (int j = 0; j < 4; j++)
                    pa[mt][j] = pe[mt][2 * kt + (j >> 1)][j & 1];
            #pragma unroll
            for (int mt = 0; mt < 2; mt++)
                #pragma unroll
                for (int nt = 0; nt < 4; nt++)
                    mma16816(o[mt][nt], pa[mt], vf[kt][nt]);
        }
    }

    // ---- reduce l across the quad (cols are spread over lanes qd) ----
    #pragma unroll
    for (int mt = 0; mt < 2; mt++)
        #pragma unroll
        for (int hf = 0; hf < 2; hf++) {
            float v = lacc[mt][hf];
            v += __shfl_xor_sync(0xffffffffu, v, 1);
            v += __shfl_xor_sync(0xffffffffu, v, 2);
            lacc[mt][hf] = v;
        }

    // ---- write O (fp16) ----
    #pragma unroll
    for (int mt = 0; mt < 2; mt++) {
        float inv0 = 1.0f / lacc[mt][0];
        float inv1 = 1.0f / lacc[mt][1];
        #pragma unroll
        for (int nt = 0; nt < 4; nt++) {
            int q = q0 + mt * 16 + grp;
            int d = nt * 8 + qd * 2;
            size_t off0 = (mbase + q) * D + h * HD + d;
            size_t off1 = (mbase + q + 8) * D + h * HD + d;
            *(uint32_t*)&g_o[off0] = packh2(o[mt][nt][0] * inv0, o[mt][nt][1] * inv0);
            *(uint32_t*)&g_o[off1] = packh2(o[mt][nt][2] * inv1, o[mt][nt][3] * inv1);
        }
    }
}

// ---------------------------------------------------------------------------
// Launch
// ---------------------------------------------------------------------------
extern "C" void kernel_launch(void* const* d_in, const int* in_sizes, int n_in,
                              void* d_out, int out_size) {
    const float* z      = (const float*)d_in[0];
    const float* ln_g   = (const float*)d_in[1];
    const float* ln_b   = (const float*)d_in[2];
    const float* w_qkv  = (const float*)d_in[3];
    const float* b_qkv  = (const float*)d_in[4];
    const float* w_proj = (const float*)d_in[5];
    const float* b_proj = (const float*)d_in[6];
    float* out = (float*)d_out;

    const int GEMM_SMEM = 2 * 128 * 128 * 2;       //  65536 B
    const int ATTN_SMEM = 3 * 256 * APITCH * 2;    //  61440 B
    cudaFuncSetAttribute(gemm_kernel<0>,
                         cudaFuncAttributeMaxDynamicSharedMemorySize, GEMM_SMEM);
    cudaFuncSetAttribute(gemm_kernel<1>,
                         cudaFuncAttributeMaxDynamicSharedMemorySize, GEMM_SMEM);
    cudaFuncSetAttribute(attn_kernel,
                         cudaFuncAttributeMaxDynamicSharedMemorySize, ATTN_SMEM);

    // 1) LN -> zn fp16 and weight casts, one launch
    ln_cast_kernel<<<LN_BLOCKS + CAST_BLOCKS, 256>>>(z, ln_g, ln_b, w_qkv, w_proj);
    // 2) QKV GEMM -> fp16 (Q pre-scaled)
    gemm_kernel<0><<<dim3(QKV_N / 128, M_TOTAL / 128), 256, GEMM_SMEM>>>(
        b_qkv, nullptr, nullptr);
    // 3) attention -> O fp16
    attn_kernel<<<dim3(NH, L), 256, ATTN_SMEM>>>();
    // 4) proj + bias + residual -> out (fp32)
    gemm_kernel<1><<<dim3(1, M_TOTAL / 128), 256, GEMM_SMEM>>>(
        b_proj, z, out);
}